// round 2
// baseline (speedup 1.0000x reference)
#include <cuda_runtime.h>

#define NB 16
#define NC 3
#define IH 720
#define IW 1280
#define OUT 255
#define PER_B (NC*IH*IW)        /* 2764800 floats per batch image */
#define PER_B4 (PER_B/4)        /* 691200 float4 per batch image */
#define RBLK 64                 /* reduction blocks per batch */

__device__ float d_partial[NB * RBLK];
__device__ float d_mean[NB];

// ---------------------------------------------------------------------------
// Kernel 1: per-batch partial sums. grid = (RBLK, NB), block = 256.
// Deterministic: each block owns a fixed slice, tree-reduced in smem.
// ---------------------------------------------------------------------------
__global__ void reduce_kernel(const float* __restrict__ im) {
    const int b   = blockIdx.y;
    const int blk = blockIdx.x;
    const float4* p = (const float4*)(im + (size_t)b * PER_B);

    float s = 0.0f;
    for (int i = blk * blockDim.x + threadIdx.x; i < PER_B4; i += RBLK * blockDim.x) {
        float4 v = p[i];
        s += (v.x + v.y) + (v.z + v.w);
    }

    __shared__ float sm[256];
    sm[threadIdx.x] = s;
    __syncthreads();
    for (int o = 128; o > 0; o >>= 1) {
        if (threadIdx.x < o) sm[threadIdx.x] += sm[threadIdx.x + o];
        __syncthreads();
    }
    if (threadIdx.x == 0) d_partial[b * RBLK + blk] = sm[0];
}

// ---------------------------------------------------------------------------
// Kernel 2: finalize means. 1 block of 512 threads = 16 warps, warp w -> batch w.
// ---------------------------------------------------------------------------
__global__ void finalize_kernel() {
    const int b = threadIdx.x >> 5;
    const int l = threadIdx.x & 31;
    float s = d_partial[b * RBLK + l] + d_partial[b * RBLK + 32 + l];
    #pragma unroll
    for (int o = 16; o > 0; o >>= 1) s += __shfl_down_sync(0xffffffffu, s, o);
    if (l == 0) d_mean[b] = s * (1.0f / (float)PER_B);
}

// ---------------------------------------------------------------------------
// Kernel 3: fused crop + mean-pad + bilinear resize (align_corners=False).
// One thread per output pixel.
// ---------------------------------------------------------------------------
__global__ void bilinear_kernel(const float* __restrict__ im,
                                const float* __restrict__ pos,
                                const float* __restrict__ szs,
                                float* __restrict__ out) {
    const int idx = blockIdx.x * blockDim.x + threadIdx.x;
    const int total = NB * NC * OUT * OUT;
    if (idx >= total) return;

    int ox = idx % OUT;
    int t  = idx / OUT;
    int oy = t % OUT;
    t /= OUT;
    int c = t % NC;
    int b = t / NC;

    const float sz    = __ldg(&szs[b]);
    const float half  = (sz + 1.0f) * 0.5f;
    const float xmin  = rintf(__ldg(&pos[2 * b + 0]) - half);  // round-half-even, matches jnp.round
    const float ymin  = rintf(__ldg(&pos[2 * b + 1]) - half);
    const float scale = sz / (float)OUT;
    const float szm1  = sz - 1.0f;
    const float avg   = d_mean[b];

    // source coords in crop space, clipped to [0, sz-1]
    float sx = fminf(fmaxf(((float)ox + 0.5f) * scale - 0.5f, 0.0f), szm1);
    float lx = floorf(sx);
    float wx = sx - lx;
    float hx = fminf(lx + 1.0f, szm1);

    float sy = fminf(fmaxf(((float)oy + 0.5f) * scale - 0.5f, 0.0f), szm1);
    float ly = floorf(sy);
    float wy = sy - ly;
    float hy = fminf(ly + 1.0f, szm1);

    // image-space sample coordinates (integer-valued floats)
    float y0 = ly + ymin, y1 = hy + ymin;
    float x0 = lx + xmin, x1 = hx + xmin;

    const float* base = im + ((size_t)b * NC + c) * (size_t)(IH * IW);

    auto gather = [&](float yf, float xf) -> float {
        bool valid = (yf >= 0.0f) & (yf <= (float)(IH - 1)) &
                     (xf >= 0.0f) & (xf <= (float)(IW - 1));
        int yc = (int)fminf(fmaxf(yf, 0.0f), (float)(IH - 1));
        int xc = (int)fminf(fmaxf(xf, 0.0f), (float)(IW - 1));
        float pix = __ldg(&base[yc * IW + xc]);   // clamped addr always in-bounds
        return valid ? pix : avg;
    };

    float v00 = gather(y0, x0);
    float v01 = gather(y0, x1);
    float v10 = gather(y1, x0);
    float v11 = gather(y1, x1);

    float top = v00 * (1.0f - wx) + v01 * wx;
    float bot = v10 * (1.0f - wx) + v11 * wx;
    out[idx]  = top * (1.0f - wy) + bot * wy;
}

// ---------------------------------------------------------------------------
extern "C" void kernel_launch(void* const* d_in, const int* in_sizes, int n_in,
                              void* d_out, int out_size) {
    const float* im  = (const float*)d_in[0];
    const float* pos = (const float*)d_in[1];
    const float* szs = (const float*)d_in[2];
    float* out = (float*)d_out;

    reduce_kernel<<<dim3(RBLK, NB), 256>>>(im);
    finalize_kernel<<<1, 512>>>();

    const int total = NB * NC * OUT * OUT;
    bilinear_kernel<<<(total + 255) / 256, 256>>>(im, pos, szs, out);
}